// round 2
// baseline (speedup 1.0000x reference)
#include <cuda_runtime.h>
#include <cstdint>

#define Bz   32
#define NV   12000
#define NT   20000
#define N1c  4000
#define N2c  1000
#define N12c 5000
#define KKc  20000

#define MTILE 512
#define KT    16
// GEMM1: M=4000 -> 8 mtiles (4096 rows), Ksplit 37, chunk 544
#define MT1 8
#define MR1 4096
#define KS1 37
#define CH1 544
// GEMM2: M=5000 -> 10 mtiles (5120 rows), Ksplit 29, chunk 704
#define MT2 10
#define MR2 5120
#define KS2 29
#define CH2 704

// ---------------- device scratch (static; no allocations) ----------------
__device__ float  g_px[NV * Bz];           // [v*32 + b]
__device__ float  g_py[NV * Bz];
__device__ float  g_pz[NV * Bz];
__device__ float2 g_dT[NT * 16];           // [t*16 + b2]
__device__ float2 g_cy[N1c * 16];          // coeffy  [i*16 + b2]
__device__ float2 g_cz[N12c * 16];         // coeffz
__device__ float2 g_P[(size_t)KS1 * MR1 * 16];  // K-split partial slab (19.4MB)
__device__ float2 g_volP[1250 * 16];
__device__ float  g_volcP[1250];
__device__ float  g_a[Bz];
__device__ float  g_sy[Bz];
__device__ float  g_sz[Bz];

// ---------------- K0: build SoA points (batch-fastest) + zero sums --------
__global__ void k_init(const float* __restrict__ x, const float* __restrict__ y,
                       const float* __restrict__ p0) {
    int u = blockIdx.x * 256 + threadIdx.x;
    if (u < 64) { if (u < 32) g_sy[u] = 0.f; else g_sz[u - 32] = 0.f; }
    if (u >= NV * Bz) return;
    int v = u >> 5, b = u & 31;
    float px, py, pz;
    if (v < N1c) {
        const float* xb = x + (size_t)b * (N1c * 3) + v * 3;
        px = xb[0]; py = xb[1]; pz = xb[2];
    } else if (v < N12c) {
        int j = v - N1c;
        const float* yb = y + (size_t)b * (N2c * 2) + j * 2;
        px = yb[0]; pz = yb[1]; py = p0[v * 3 + 1];
    } else {
        px = p0[v * 3]; py = p0[v * 3 + 1]; pz = p0[v * 3 + 2];
    }
    g_px[u] = px; g_py[u] = py; g_pz[u] = pz;
}

// ---------------- K1: per-triangle dets (phase0: det_y + vol, phase1: det_z)
__global__ void k_det(const int* __restrict__ tri, const float* __restrict__ p0,
                      int phase) {
    __shared__ float2 sv[16];
    __shared__ float  sc;
    int tid = threadIdx.x;
    if (phase == 0) {
        if (tid < 16) sv[tid] = make_float2(0.f, 0.f);
        if (tid == 0) sc = 0.f;
        __syncthreads();
    }
    int u = blockIdx.x * 256 + tid;
    int t = u >> 4, b2 = u & 15;
    if (t < NT) {
        int v0 = tri[t * 3], v1 = tri[t * 3 + 1], v2 = tri[t * 3 + 2];
        const float2* PX = (const float2*)g_px;
        const float2* PY = (const float2*)g_py;
        const float2* PZ = (const float2*)g_pz;
        float2 x0 = PX[v0 * 16 + b2], x1 = PX[v1 * 16 + b2], x2 = PX[v2 * 16 + b2];
        if (phase == 0) {
            float2 z0 = PZ[v0 * 16 + b2], z1 = PZ[v1 * 16 + b2], z2 = PZ[v2 * 16 + b2];
            float2 y0 = PY[v0 * 16 + b2], y1 = PY[v1 * 16 + b2], y2 = PY[v2 * 16 + b2];
            float2 dy;
            dy.x = ((x0.x - x1.x) * (z2.x - z1.x) - (z0.x - z1.x) * (x2.x - x1.x)) * (1.f / 6.f);
            dy.y = ((x0.y - x1.y) * (z2.y - z1.y) - (z0.y - z1.y) * (x2.y - x1.y)) * (1.f / 6.f);
            g_dT[t * 16 + b2] = dy;
            atomicAdd(&sv[b2].x, (y0.x + y1.x + y2.x) * dy.x);
            atomicAdd(&sv[b2].y, (y0.y + y1.y + y2.y) * dy.y);
            if (b2 == 0) {  // batch-independent base-mesh volume
                float X0 = p0[v0 * 3], Y0 = p0[v0 * 3 + 1], Z0 = p0[v0 * 3 + 2];
                float X1 = p0[v1 * 3], Y1 = p0[v1 * 3 + 1], Z1 = p0[v1 * 3 + 2];
                float X2 = p0[v2 * 3], Y2 = p0[v2 * 3 + 1], Z2 = p0[v2 * 3 + 2];
                float d0 = ((X0 - X1) * (Z2 - Z1) - (Z0 - Z1) * (X2 - X1)) * (1.f / 6.f);
                atomicAdd(&sc, (Y0 + Y1 + Y2) * d0);
            }
        } else {
            float2 y0 = PY[v0 * 16 + b2], y1 = PY[v1 * 16 + b2], y2 = PY[v2 * 16 + b2];
            float2 dz;
            dz.x = ((x0.x - x2.x) * (y1.x - y2.x) - (y0.x - y2.x) * (x1.x - x2.x)) * (1.f / 6.f);
            dz.y = ((x0.y - x2.y) * (y1.y - y2.y) - (y0.y - y2.y) * (x1.y - x2.y)) * (1.f / 6.f);
            g_dT[t * 16 + b2] = dz;
        }
    }
    if (phase == 0) {
        __syncthreads();
        if (tid < 16) g_volP[blockIdx.x * 16 + tid] = sv[tid];
        if (tid == 0) g_volcP[blockIdx.x] = sc;
    }
}

// ---------------- K2: reduce volume partials -> a[b] ----------------------
__global__ void k_a() {
    __shared__ float2 red[256];
    __shared__ float  redc[256];
    int tid = threadIdx.x;
    int b2 = tid & 15, r = tid >> 4;
    float2 s = make_float2(0.f, 0.f);
    for (int j = r; j < 1250; j += 16) {
        float2 v = g_volP[j * 16 + b2]; s.x += v.x; s.y += v.y;
    }
    red[tid] = s;
    float c = 0.f;
    for (int j = tid; j < 1250; j += 256) c += g_volcP[j];
    redc[tid] = c;
    __syncthreads();
    for (int h = 8; h > 0; h >>= 1) {
        if (r < h) { red[tid].x += red[tid + h * 16].x; red[tid].y += red[tid + h * 16].y; }
        __syncthreads();
    }
    for (int h = 128; h > 0; h >>= 1) {
        if (tid < h) redc[tid] += redc[tid + h];
        __syncthreads();
    }
    if (tid < 32) {
        float volc = redc[0];
        float2 vb = red[tid >> 1];
        float volb = (tid & 1) ? vb.y : vb.x;
        g_a[tid] = 0.5f * (volc - volb);
    }
}

// ---------------- GEMM: slab[ky][i][b2] += A[i][k]*dT[k][b2]  (f32x2) -----
__global__ void __launch_bounds__(128, 2)
k_gemm(const float* __restrict__ A, int M, int CH, int Mrows) {
    __shared__ float As[KT * 516];                 // [k][i] transposed, padded
    __shared__ __align__(16) float2 ds[KT * 18];   // [k][b2], padded
    int tid = threadIdx.x;
    int bg = tid & 1, ig = tid >> 1;
    int iLoc = ig * 8;
    int ibase = blockIdx.x * MTILE;
    int k0 = blockIdx.y * CH;
    int kend = min(KKc, k0 + CH);

    uint64_t acc[8][8];
#pragma unroll
    for (int r2 = 0; r2 < 8; r2++)
#pragma unroll
        for (int c2 = 0; c2 < 8; c2++) acc[r2][c2] = 0ull;

    int k4 = (tid & 3) * 4;
    int iL0 = tid >> 2;

    for (int kt = k0; kt < kend; kt += KT) {
        // stage A tile (512 rows x 16 k) transposed into smem
#pragma unroll
        for (int s = 0; s < 16; s++) {
            int iL = iL0 + s * 32;
            int gi = ibase + iL;
            float4 v = make_float4(0.f, 0.f, 0.f, 0.f);
            if (gi < M) v = *(const float4*)(A + (size_t)gi * KKc + kt + k4);
            As[(k4 + 0) * 516 + iL] = v.x;
            As[(k4 + 1) * 516 + iL] = v.y;
            As[(k4 + 2) * 516 + iL] = v.z;
            As[(k4 + 3) * 516 + iL] = v.w;
        }
        // stage dT tile (16 k x 16 f2)
        {
            float4 v = ((const float4*)(g_dT + (size_t)kt * 16))[tid];
            int kl = tid >> 3, bb = (tid & 7) * 2;
            ds[kl * 18 + bb]     = make_float2(v.x, v.y);
            ds[kl * 18 + bb + 1] = make_float2(v.z, v.w);
        }
        __syncthreads();
#pragma unroll 4
        for (int kl = 0; kl < KT; kl++) {
            float4 a01 = *(const float4*)&As[kl * 516 + iLoc];
            float4 a23 = *(const float4*)&As[kl * 516 + iLoc + 4];
            const ulonglong2* dp = (const ulonglong2*)&ds[kl * 18 + bg * 8];
            ulonglong2 q0 = dp[0], q1 = dp[1], q2 = dp[2], q3 = dp[3];
            uint64_t d[8] = {q0.x, q0.y, q1.x, q1.y, q2.x, q2.y, q3.x, q3.y};
            float af[8] = {a01.x, a01.y, a01.z, a01.w, a23.x, a23.y, a23.z, a23.w};
#pragma unroll
            for (int r2 = 0; r2 < 8; r2++) {
                uint64_t ap;
                asm("mov.b64 %0, {%1, %1};" : "=l"(ap) : "f"(af[r2]));
#pragma unroll
                for (int c2 = 0; c2 < 8; c2++)
                    asm("fma.rn.f32x2 %0, %1, %2, %0;"
                        : "+l"(acc[r2][c2]) : "l"(ap), "l"(d[c2]));
            }
        }
        __syncthreads();
    }
    size_t slab = (size_t)blockIdx.y * Mrows * 16;
#pragma unroll
    for (int r2 = 0; r2 < 8; r2++) {
        int gi = ibase + iLoc + r2;
        float2* dst = g_P + slab + (size_t)gi * 16 + bg * 8;
#pragma unroll
        for (int c2 = 0; c2 < 8; c2++) {
            float2 val;
            asm("mov.b64 {%0, %1}, %2;" : "=f"(val.x), "=f"(val.y) : "l"(acc[r2][c2]));
            dst[c2] = val;
        }
    }
}

// ---------------- fold K-split partials -> coeff, s[b] = sum coeff^2 ------
__global__ void k_reduce(int phase) {
    __shared__ float sAcc[32];
    int tid = threadIdx.x;
    if (tid < 32) sAcc[tid] = 0.f;
    __syncthreads();
    int Ksp   = phase ? KS2 : KS1;
    int Mrows = phase ? MR2 : MR1;
    int M     = phase ? N12c : N1c;
    float2* coeff = phase ? g_cz : g_cy;
    float*  sOut  = phase ? g_sz : g_sy;
    int u = blockIdx.x * 256 + tid;
    int i = u >> 4, b2 = u & 15;
    if (i < M) {
        float2 s = make_float2(0.f, 0.f);
        for (int j = 0; j < Ksp; j++) {
            float2 v = g_P[(size_t)j * Mrows * 16 + u];
            s.x += v.x; s.y += v.y;
        }
        coeff[u] = s;
        atomicAdd(&sAcc[b2 * 2],     s.x * s.x);
        atomicAdd(&sAcc[b2 * 2 + 1], s.y * s.y);
    }
    __syncthreads();
    if (tid < 32) atomicAdd(&sOut[tid], sAcc[tid]);
}

// ---------------- apply rank-1 y correction to vertices < N1 --------------
__global__ void k_upy() {
    int u = blockIdx.x * 256 + threadIdx.x;
    if (u >= N1c * Bz) return;
    int b = u & 31;
    float cy = ((const float*)g_cy)[u];
    g_py[u] += cy * (g_a[b] / g_sy[b]);
}

// ---------------- final outputs (z correction applied on the fly) ---------
__global__ void k_out(float* __restrict__ out) {
    int u = blockIdx.x * 256 + threadIdx.x;
    if (u >= N12c * Bz) return;
    int v = u >> 5, b = u & 31;
    float corr = ((const float*)g_cz)[u] * (g_a[b] / g_sz[b]);
    float X = g_px[u], Z = g_pz[u] + corr;
    if (v < N1c) {
        float* o = out + (size_t)b * (N1c * 3) + v * 3;
        o[0] = X; o[1] = g_py[u]; o[2] = Z;
    } else {
        int j = v - N1c;
        float* o = out + (size_t)Bz * N1c * 3 + (size_t)b * (N2c * 2) + j * 2;
        o[0] = X; o[1] = Z;
    }
}

extern "C" void kernel_launch(void* const* d_in, const int* in_sizes, int n_in,
                              void* d_out, int out_size) {
    const float* x   = (const float*)d_in[0];
    const float* y   = (const float*)d_in[1];
    const float* p0  = (const float*)d_in[2];
    const int*   tri = (const int*)d_in[3];
    const float* Vx  = (const float*)d_in[6];
    const float* Vxy = (const float*)d_in[7];
    float* out = (float*)d_out;
    (void)in_sizes; (void)n_in; (void)out_size;

    k_init<<<1500, 256>>>(x, y, p0);
    k_det<<<1250, 256>>>(tri, p0, 0);
    k_a<<<1, 256>>>();
    k_gemm<<<dim3(MT1, KS1), 128>>>(Vx, N1c, CH1, MR1);
    k_reduce<<<250, 256>>>(0);
    k_upy<<<500, 256>>>();
    k_det<<<1250, 256>>>(tri, p0, 1);
    k_gemm<<<dim3(MT2, KS2), 128>>>(Vxy, N12c, CH2, MR2);
    k_reduce<<<313, 256>>>(1);
    k_out<<<625, 256>>>(out);
}

// round 3
// speedup vs baseline: 1.1030x; 1.1030x over previous
#include <cuda_runtime.h>
#include <cstdint>

#define Bz   32
#define NV   12000
#define NT   20000
#define N1c  4000
#define N2c  1000
#define N12c 5000
#define KKc  20000

#define MTILE 512
#define KT    8
// GEMM1: M=4000 -> 8 mtiles (4096 rows), Ksplit 37, chunk 544 (68 KT-tiles)
#define MT1 8
#define MR1 4096
#define KS1 37
#define CH1 544
// GEMM2: M=5000 -> 10 mtiles (5120 rows), Ksplit 29, chunk 696 (87 KT-tiles)
#define MT2 10
#define MR2 5120
#define KS2 29
#define CH2 696

// ---------------- device scratch (static; no allocations) ----------------
__device__ float  g_px[NV * Bz];           // [v*32 + b]
__device__ float  g_py[NV * Bz];
__device__ float  g_pz[NV * Bz];
__device__ __align__(16) float2 g_dT[NT * 16];   // [t*16 + b2]
__device__ float2 g_cy[N1c * 16];          // coeffy  [i*16 + b2]
__device__ float2 g_cz[N12c * 16];         // coeffz
__device__ __align__(16) float2 g_P[(size_t)KS1 * MR1 * 16];  // partial slab
__device__ float2 g_volP[1250 * 16];
__device__ float  g_volcP[1250];
__device__ float  g_a[Bz];
__device__ float  g_sy[Bz];
__device__ float  g_sz[Bz];

// ---------------- K0: build SoA points (batch-fastest) + zero sums --------
__global__ void k_init(const float* __restrict__ x, const float* __restrict__ y,
                       const float* __restrict__ p0) {
    int u = blockIdx.x * 256 + threadIdx.x;
    if (u < 64) { if (u < 32) g_sy[u] = 0.f; else g_sz[u - 32] = 0.f; }
    if (u >= NV * Bz) return;
    int v = u >> 5, b = u & 31;
    float px, py, pz;
    if (v < N1c) {
        const float* xb = x + (size_t)b * (N1c * 3) + v * 3;
        px = xb[0]; py = xb[1]; pz = xb[2];
    } else if (v < N12c) {
        int j = v - N1c;
        const float* yb = y + (size_t)b * (N2c * 2) + j * 2;
        px = yb[0]; pz = yb[1]; py = p0[v * 3 + 1];
    } else {
        px = p0[v * 3]; py = p0[v * 3 + 1]; pz = p0[v * 3 + 2];
    }
    g_px[u] = px; g_py[u] = py; g_pz[u] = pz;
}

// ---------------- K1: per-triangle dets (phase0: det_y + vol, phase1: det_z)
__global__ void k_det(const int* __restrict__ tri, const float* __restrict__ p0,
                      int phase) {
    __shared__ float2 sv[16];
    __shared__ float  sc;
    int tid = threadIdx.x;
    if (phase == 0) {
        if (tid < 16) sv[tid] = make_float2(0.f, 0.f);
        if (tid == 0) sc = 0.f;
        __syncthreads();
    }
    int u = blockIdx.x * 256 + tid;
    int t = u >> 4, b2 = u & 15;
    if (t < NT) {
        int v0 = tri[t * 3], v1 = tri[t * 3 + 1], v2 = tri[t * 3 + 2];
        const float2* PX = (const float2*)g_px;
        const float2* PY = (const float2*)g_py;
        const float2* PZ = (const float2*)g_pz;
        float2 x0 = PX[v0 * 16 + b2], x1 = PX[v1 * 16 + b2], x2 = PX[v2 * 16 + b2];
        if (phase == 0) {
            float2 z0 = PZ[v0 * 16 + b2], z1 = PZ[v1 * 16 + b2], z2 = PZ[v2 * 16 + b2];
            float2 y0 = PY[v0 * 16 + b2], y1 = PY[v1 * 16 + b2], y2 = PY[v2 * 16 + b2];
            float2 dy;
            dy.x = ((x0.x - x1.x) * (z2.x - z1.x) - (z0.x - z1.x) * (x2.x - x1.x)) * (1.f / 6.f);
            dy.y = ((x0.y - x1.y) * (z2.y - z1.y) - (z0.y - z1.y) * (x2.y - x1.y)) * (1.f / 6.f);
            g_dT[t * 16 + b2] = dy;
            atomicAdd(&sv[b2].x, (y0.x + y1.x + y2.x) * dy.x);
            atomicAdd(&sv[b2].y, (y0.y + y1.y + y2.y) * dy.y);
            if (b2 == 0) {
                float X0 = p0[v0 * 3], Y0 = p0[v0 * 3 + 1], Z0 = p0[v0 * 3 + 2];
                float X1 = p0[v1 * 3], Y1 = p0[v1 * 3 + 1], Z1 = p0[v1 * 3 + 2];
                float X2 = p0[v2 * 3], Y2 = p0[v2 * 3 + 1], Z2 = p0[v2 * 3 + 2];
                float d0 = ((X0 - X1) * (Z2 - Z1) - (Z0 - Z1) * (X2 - X1)) * (1.f / 6.f);
                atomicAdd(&sc, (Y0 + Y1 + Y2) * d0);
            }
        } else {
            float2 y0 = PY[v0 * 16 + b2], y1 = PY[v1 * 16 + b2], y2 = PY[v2 * 16 + b2];
            float2 dz;
            dz.x = ((x0.x - x2.x) * (y1.x - y2.x) - (y0.x - y2.x) * (x1.x - x2.x)) * (1.f / 6.f);
            dz.y = ((x0.y - x2.y) * (y1.y - y2.y) - (y0.y - y2.y) * (x1.y - x2.y)) * (1.f / 6.f);
            g_dT[t * 16 + b2] = dz;
        }
    }
    if (phase == 0) {
        __syncthreads();
        if (tid < 16) g_volP[blockIdx.x * 16 + tid] = sv[tid];
        if (tid == 0) g_volcP[blockIdx.x] = sc;
    }
}

// ---------------- K2: reduce volume partials -> a[b] ----------------------
__global__ void k_a() {
    __shared__ float2 red[256];
    __shared__ float  redc[256];
    int tid = threadIdx.x;
    int b2 = tid & 15, r = tid >> 4;
    float2 s = make_float2(0.f, 0.f);
    for (int j = r; j < 1250; j += 16) {
        float2 v = g_volP[j * 16 + b2]; s.x += v.x; s.y += v.y;
    }
    red[tid] = s;
    float c = 0.f;
    for (int j = tid; j < 1250; j += 256) c += g_volcP[j];
    redc[tid] = c;
    __syncthreads();
    for (int h = 8; h > 0; h >>= 1) {
        if (r < h) { red[tid].x += red[tid + h * 16].x; red[tid].y += red[tid + h * 16].y; }
        __syncthreads();
    }
    for (int h = 128; h > 0; h >>= 1) {
        if (tid < h) redc[tid] += redc[tid + h];
        __syncthreads();
    }
    if (tid < 32) {
        float volc = redc[0];
        float2 vb = red[tid >> 1];
        float volb = (tid & 1) ? vb.y : vb.x;
        g_a[tid] = 0.5f * (volc - volb);
    }
}

// ---- GEMM: slab[ky][i][b2] += A[i][k]*dT[k][b2]  (f32x2, double-buffered) ----
__global__ void __launch_bounds__(256, 2)
k_gemm(const float* __restrict__ A, int M, int CH, int Mrows) {
    __shared__ float As[KT * 516];                 // [k][i] transposed
    __shared__ __align__(16) float2 ds[KT * 16];   // [k][b2]
    int tid = threadIdx.x;
    int bg = tid & 3;            // batch quarter (4 f2)
    int ig = tid >> 2;           // 0..63
    int iLoc = ig * 8;
    int ibase = blockIdx.x * MTILE;
    int k0 = blockIdx.y * CH;
    int kend = min(KKc, k0 + CH);

    uint64_t acc[8][4];
#pragma unroll
    for (int r2 = 0; r2 < 8; r2++)
#pragma unroll
        for (int c2 = 0; c2 < 4; c2++) acc[r2][c2] = 0ull;

    int k4 = (tid & 1) * 4;      // which half of the 8 k's
    int r0 = tid >> 1;           // 0..127 (row group)

    float4 areg[4];
    float4 dreg;

    // prefetch first tile into registers
#pragma unroll
    for (int s = 0; s < 4; s++) {
        int gi = ibase + r0 + s * 128;
        areg[s] = (gi < M) ? *(const float4*)(A + (size_t)gi * KKc + k0 + k4)
                           : make_float4(0.f, 0.f, 0.f, 0.f);
    }
    if (tid < 64) dreg = ((const float4*)(g_dT + (size_t)k0 * 16))[tid];

    for (int kt = k0; kt < kend; kt += KT) {
        __syncthreads();   // previous compute done before overwriting smem
#pragma unroll
        for (int s = 0; s < 4; s++) {
            int iL = r0 + s * 128;
            As[(k4 + 0) * 516 + iL] = areg[s].x;
            As[(k4 + 1) * 516 + iL] = areg[s].y;
            As[(k4 + 2) * 516 + iL] = areg[s].z;
            As[(k4 + 3) * 516 + iL] = areg[s].w;
        }
        if (tid < 64) ((float4*)ds)[tid] = dreg;
        __syncthreads();
        // prefetch next tile (overlapped with compute below)
        int ktn = kt + KT;
        if (ktn < kend) {
#pragma unroll
            for (int s = 0; s < 4; s++) {
                int gi = ibase + r0 + s * 128;
                areg[s] = (gi < M) ? *(const float4*)(A + (size_t)gi * KKc + ktn + k4)
                                   : make_float4(0.f, 0.f, 0.f, 0.f);
            }
            if (tid < 64) dreg = ((const float4*)(g_dT + (size_t)ktn * 16))[tid];
        }
#pragma unroll
        for (int kl = 0; kl < KT; kl++) {
            float4 a01 = *(const float4*)&As[kl * 516 + iLoc];
            float4 a23 = *(const float4*)&As[kl * 516 + iLoc + 4];
            ulonglong2 q0 = *(const ulonglong2*)&ds[kl * 16 + bg * 4];
            ulonglong2 q1 = *(const ulonglong2*)&ds[kl * 16 + bg * 4 + 2];
            uint64_t d[4] = {q0.x, q0.y, q1.x, q1.y};
            float af[8] = {a01.x, a01.y, a01.z, a01.w, a23.x, a23.y, a23.z, a23.w};
#pragma unroll
            for (int r2 = 0; r2 < 8; r2++) {
                uint64_t ap;
                asm("mov.b64 %0, {%1, %1};" : "=l"(ap) : "f"(af[r2]));
#pragma unroll
                for (int c2 = 0; c2 < 4; c2++)
                    asm("fma.rn.f32x2 %0, %1, %2, %0;"
                        : "+l"(acc[r2][c2]) : "l"(ap), "l"(d[c2]));
            }
        }
    }
    // write partial slab (vectorized, 16B aligned)
    size_t slab = (size_t)blockIdx.y * Mrows * 16;
#pragma unroll
    for (int r2 = 0; r2 < 8; r2++) {
        int gi = ibase + iLoc + r2;
        float2* dst = g_P + slab + (size_t)gi * 16 + bg * 4;
#pragma unroll
        for (int c2 = 0; c2 < 2; c2++) {
            float4 val;
            asm("mov.b64 {%0, %1}, %2;" : "=f"(val.x), "=f"(val.y) : "l"(acc[r2][c2 * 2]));
            asm("mov.b64 {%0, %1}, %2;" : "=f"(val.z), "=f"(val.w) : "l"(acc[r2][c2 * 2 + 1]));
            *(float4*)(dst + c2 * 2) = val;
        }
    }
}

// ---------------- fold K-split partials -> coeff, s[b] = sum coeff^2 ------
__global__ void k_reduce(int phase) {
    __shared__ float sAcc[32];
    int tid = threadIdx.x;
    if (tid < 32) sAcc[tid] = 0.f;
    __syncthreads();
    int Ksp   = phase ? KS2 : KS1;
    int Mrows = phase ? MR2 : MR1;
    int M     = phase ? N12c : N1c;
    float2* coeff = phase ? g_cz : g_cy;
    float*  sOut  = phase ? g_sz : g_sy;
    int u = blockIdx.x * 256 + tid;
    int i = u >> 4, b2 = u & 15;
    if (i < M) {
        float2 s = make_float2(0.f, 0.f);
        for (int j = 0; j < Ksp; j++) {
            float2 v = g_P[(size_t)j * Mrows * 16 + u];
            s.x += v.x; s.y += v.y;
        }
        coeff[u] = s;
        atomicAdd(&sAcc[b2 * 2],     s.x * s.x);
        atomicAdd(&sAcc[b2 * 2 + 1], s.y * s.y);
    }
    __syncthreads();
    if (tid < 32) atomicAdd(&sOut[tid], sAcc[tid]);
}

// ---------------- apply rank-1 y correction to vertices < N1 --------------
__global__ void k_upy() {
    int u = blockIdx.x * 256 + threadIdx.x;
    if (u >= N1c * Bz) return;
    int b = u & 31;
    float cy = ((const float*)g_cy)[u];
    g_py[u] += cy * (g_a[b] / g_sy[b]);
}

// ---------------- final outputs (z correction applied on the fly) ---------
__global__ void k_out(float* __restrict__ out) {
    int u = blockIdx.x * 256 + threadIdx.x;
    if (u >= N12c * Bz) return;
    int v = u >> 5, b = u & 31;
    float corr = ((const float*)g_cz)[u] * (g_a[b] / g_sz[b]);
    float X = g_px[u], Z = g_pz[u] + corr;
    if (v < N1c) {
        float* o = out + (size_t)b * (N1c * 3) + v * 3;
        o[0] = X; o[1] = g_py[u]; o[2] = Z;
    } else {
        int j = v - N1c;
        float* o = out + (size_t)Bz * N1c * 3 + (size_t)b * (N2c * 2) + j * 2;
        o[0] = X; o[1] = Z;
    }
}

extern "C" void kernel_launch(void* const* d_in, const int* in_sizes, int n_in,
                              void* d_out, int out_size) {
    const float* x   = (const float*)d_in[0];
    const float* y   = (const float*)d_in[1];
    const float* p0  = (const float*)d_in[2];
    const int*   tri = (const int*)d_in[3];
    const float* Vx  = (const float*)d_in[6];
    const float* Vxy = (const float*)d_in[7];
    float* out = (float*)d_out;
    (void)in_sizes; (void)n_in; (void)out_size;

    k_init<<<1500, 256>>>(x, y, p0);
    k_det<<<1250, 256>>>(tri, p0, 0);
    k_a<<<1, 256>>>();
    k_gemm<<<dim3(MT1, KS1), 256>>>(Vx, N1c, CH1, MR1);
    k_reduce<<<250, 256>>>(0);
    k_upy<<<500, 256>>>();
    k_det<<<1250, 256>>>(tri, p0, 1);
    k_gemm<<<dim3(MT2, KS2), 256>>>(Vxy, N12c, CH2, MR2);
    k_reduce<<<313, 256>>>(1);
    k_out<<<625, 256>>>(out);
}

// round 4
// speedup vs baseline: 1.4846x; 1.3460x over previous
#include <cuda_runtime.h>
#include <cuda_bf16.h>
#include <cstdint>

#define Bz   32
#define NV   12000
#define NT   20000
#define N1c  4000
#define N2c  1000
#define N12c 5000
#define KKc  20000
#define KC   625            // number of 32-wide k-chunks (625*32 = 20000 exactly)

// GEMM1: 32 m-tiles (4096 rows), Ksplit 9 (70 chunks/split, last 65)
#define MT1 32
#define MR1 4096
#define KS1 9
#define CPS1 70
// GEMM2: 40 m-tiles (5120 rows), Ksplit 7 (90 chunks/split, last 85)
#define MT2 40
#define MR2 5120
#define KS2 7
#define CPS2 90

#define APITCH 40   // bf16 elems per A smem row (80B: 16B-aligned, ldmatrix conflict-free)
#define BPITCH 40

// ---------------- device scratch (static; no allocations) ----------------
__device__ float  g_px[NV * Bz];            // [v*32 + b]
__device__ float  g_py[NV * Bz];
__device__ float  g_pz[NV * Bz];
__device__ __nv_bfloat16 g_Bh[NT * Bz];     // B hi split, [t*32 + b]
__device__ __nv_bfloat16 g_Bl[NT * Bz];     // B lo split
__device__ float  g_cy[N1c * Bz];           // coeffy [i*32 + b]
__device__ float  g_cz[N12c * Bz];
__device__ float  g_Pf[(size_t)KS1 * MR1 * 32];  // K-split partial slab (4.7MB)
__device__ float2 g_volP[1250 * 16];
__device__ float  g_volcP[1250];
__device__ float  g_a[Bz];
__device__ float  g_sy[Bz];
__device__ float  g_sz[Bz];

// ---------------- K0: build SoA points (batch-fastest) + zero sums --------
__global__ void k_init(const float* __restrict__ x, const float* __restrict__ y,
                       const float* __restrict__ p0) {
    int u = blockIdx.x * 256 + threadIdx.x;
    if (u < 64) { if (u < 32) g_sy[u] = 0.f; else g_sz[u - 32] = 0.f; }
    if (u >= NV * Bz) return;
    int v = u >> 5, b = u & 31;
    float px, py, pz;
    if (v < N1c) {
        const float* xb = x + (size_t)b * (N1c * 3) + v * 3;
        px = xb[0]; py = xb[1]; pz = xb[2];
    } else if (v < N12c) {
        int j = v - N1c;
        const float* yb = y + (size_t)b * (N2c * 2) + j * 2;
        px = yb[0]; pz = yb[1]; py = p0[v * 3 + 1];
    } else {
        px = p0[v * 3]; py = p0[v * 3 + 1]; pz = p0[v * 3 + 2];
    }
    g_px[u] = px; g_py[u] = py; g_pz[u] = pz;
}

// helper: split a pair of floats into bf16 hi/lo packed bfloat162
__device__ __forceinline__ void split2(float f0, float f1, unsigned& hw, unsigned& lw) {
    __nv_bfloat162 h = __floats2bfloat162_rn(f0, f1);
    float r0 = f0 - __bfloat162float(h.x);
    float r1 = f1 - __bfloat162float(h.y);
    __nv_bfloat162 l = __floats2bfloat162_rn(r0, r1);
    hw = *(unsigned*)&h; lw = *(unsigned*)&l;
}

// ---------------- K1: per-triangle dets -> bf16-split B, + volume ---------
__global__ void k_det(const int* __restrict__ tri, const float* __restrict__ p0,
                      int phase) {
    __shared__ float2 sv[16];
    __shared__ float  sc;
    int tid = threadIdx.x;
    if (phase == 0) {
        if (tid < 16) sv[tid] = make_float2(0.f, 0.f);
        if (tid == 0) sc = 0.f;
        __syncthreads();
    }
    int u = blockIdx.x * 256 + tid;
    int t = u >> 4, b2 = u & 15;
    if (t < NT) {
        int v0 = tri[t * 3], v1 = tri[t * 3 + 1], v2 = tri[t * 3 + 2];
        const float2* PX = (const float2*)g_px;
        const float2* PY = (const float2*)g_py;
        const float2* PZ = (const float2*)g_pz;
        float2 x0 = PX[v0 * 16 + b2], x1 = PX[v1 * 16 + b2], x2 = PX[v2 * 16 + b2];
        float2 d;
        if (phase == 0) {
            float2 z0 = PZ[v0 * 16 + b2], z1 = PZ[v1 * 16 + b2], z2 = PZ[v2 * 16 + b2];
            float2 y0 = PY[v0 * 16 + b2], y1 = PY[v1 * 16 + b2], y2 = PY[v2 * 16 + b2];
            d.x = ((x0.x - x1.x) * (z2.x - z1.x) - (z0.x - z1.x) * (x2.x - x1.x)) * (1.f / 6.f);
            d.y = ((x0.y - x1.y) * (z2.y - z1.y) - (z0.y - z1.y) * (x2.y - x1.y)) * (1.f / 6.f);
            atomicAdd(&sv[b2].x, (y0.x + y1.x + y2.x) * d.x);
            atomicAdd(&sv[b2].y, (y0.y + y1.y + y2.y) * d.y);
            if (b2 == 0) {
                float X0 = p0[v0 * 3], Y0 = p0[v0 * 3 + 1], Z0 = p0[v0 * 3 + 2];
                float X1 = p0[v1 * 3], Y1 = p0[v1 * 3 + 1], Z1 = p0[v1 * 3 + 2];
                float X2 = p0[v2 * 3], Y2 = p0[v2 * 3 + 1], Z2 = p0[v2 * 3 + 2];
                float d0 = ((X0 - X1) * (Z2 - Z1) - (Z0 - Z1) * (X2 - X1)) * (1.f / 6.f);
                atomicAdd(&sc, (Y0 + Y1 + Y2) * d0);
            }
        } else {
            float2 y0 = PY[v0 * 16 + b2], y1 = PY[v1 * 16 + b2], y2 = PY[v2 * 16 + b2];
            d.x = ((x0.x - x2.x) * (y1.x - y2.x) - (y0.x - y2.x) * (x1.x - x2.x)) * (1.f / 6.f);
            d.y = ((x0.y - x2.y) * (y1.y - y2.y) - (y0.y - y2.y) * (x1.y - x2.y)) * (1.f / 6.f);
        }
        unsigned hw, lw;
        split2(d.x, d.y, hw, lw);
        *(unsigned*)(g_Bh + t * 32 + 2 * b2) = hw;
        *(unsigned*)(g_Bl + t * 32 + 2 * b2) = lw;
    }
    if (phase == 0) {
        __syncthreads();
        if (tid < 16) g_volP[blockIdx.x * 16 + tid] = sv[tid];
        if (tid == 0) g_volcP[blockIdx.x] = sc;
    }
}

// ---------------- K2: reduce volume partials -> a[b] ----------------------
__global__ void k_a() {
    __shared__ float2 red[256];
    __shared__ float  redc[256];
    int tid = threadIdx.x;
    int b2 = tid & 15, r = tid >> 4;
    float2 s = make_float2(0.f, 0.f);
    for (int j = r; j < 1250; j += 16) {
        float2 v = g_volP[j * 16 + b2]; s.x += v.x; s.y += v.y;
    }
    red[tid] = s;
    float c = 0.f;
    for (int j = tid; j < 1250; j += 256) c += g_volcP[j];
    redc[tid] = c;
    __syncthreads();
    for (int h = 8; h > 0; h >>= 1) {
        if (r < h) { red[tid].x += red[tid + h * 16].x; red[tid].y += red[tid + h * 16].y; }
        __syncthreads();
    }
    for (int h = 128; h > 0; h >>= 1) {
        if (tid < h) redc[tid] += redc[tid + h];
        __syncthreads();
    }
    if (tid < 32) {
        float volc = redc[0];
        float2 vb = red[tid >> 1];
        float volb = (tid & 1) ? vb.y : vb.x;
        g_a[tid] = 0.5f * (volc - volb);
    }
}

// ---------------- tensor-core GEMM (bf16-split, mma.sync m16n8k16) --------
#define LDSM4(r, addr) \
    asm volatile("ldmatrix.sync.aligned.m8n8.x4.shared.b16 {%0,%1,%2,%3}, [%4];" \
        : "=r"((r)[0]), "=r"((r)[1]), "=r"((r)[2]), "=r"((r)[3]) : "r"(addr))
#define LDSM2T(r, addr) \
    asm volatile("ldmatrix.sync.aligned.m8n8.x2.trans.shared.b16 {%0,%1}, [%2];" \
        : "=r"((r)[0]), "=r"((r)[1]) : "r"(addr))
#define MMABF16(dd, aa, bb) \
    asm volatile("mma.sync.aligned.m16n8k16.row.col.f32.bf16.bf16.f32 " \
        "{%0,%1,%2,%3}, {%4,%5,%6,%7}, {%8,%9}, {%0,%1,%2,%3};" \
        : "+f"((dd)[0]), "+f"((dd)[1]), "+f"((dd)[2]), "+f"((dd)[3]) \
        : "r"((aa)[0]), "r"((aa)[1]), "r"((aa)[2]), "r"((aa)[3]), \
          "r"((bb)[0]), "r"((bb)[1]))

__global__ void __launch_bounds__(256, 2)
k_gemm_tc(const float* __restrict__ A, int M, int Mrows, int cps) {
    extern __shared__ __align__(16) __nv_bfloat16 sm[];
    __nv_bfloat16* Ah = sm;                              // 2 x 128 x APITCH
    __nv_bfloat16* Al = Ah + 2 * 128 * APITCH;
    __nv_bfloat16* Bhs = Al + 2 * 128 * APITCH;          // 2 x 32 x BPITCH
    __nv_bfloat16* Bls = Bhs + 2 * 32 * BPITCH;

    int tid = threadIdx.x;
    int lane = tid & 31, w = tid >> 5;
    int wm = w >> 1, wn = w & 1;
    int ibase = blockIdx.x * 128;
    int c0 = blockIdx.y * cps;
    int c1 = min(KC, c0 + cps);

    int am = tid >> 1;
    int ak = (tid & 1) * 16;
    const float* Arow = A + (size_t)(ibase + am) * KKc + ak;
    bool aval = (ibase + am) < M;
    int bk = tid >> 3;
    int bn = (tid & 7) * 4;

    float4 ar[4];
    uint2 bhr, blr;
    {
        int kb = c0 * 32;
#pragma unroll
        for (int j = 0; j < 4; j++)
            ar[j] = aval ? *(const float4*)(Arow + kb + j * 4) : make_float4(0,0,0,0);
        bhr = *(const uint2*)(g_Bh + (size_t)(kb + bk) * 32 + bn);
        blr = *(const uint2*)(g_Bl + (size_t)(kb + bk) * 32 + bn);
    }

    float d[2][2][4];
#pragma unroll
    for (int mt = 0; mt < 2; mt++)
#pragma unroll
        for (int nt = 0; nt < 2; nt++)
#pragma unroll
            for (int q = 0; q < 4; q++) d[mt][nt][q] = 0.f;

    int p = 0;
    for (int c = c0; c < c1; c++) {
        __syncthreads();
        {
            __nv_bfloat16* ah = Ah + p * 128 * APITCH + am * APITCH + ak;
            __nv_bfloat16* al = Al + p * 128 * APITCH + am * APITCH + ak;
#pragma unroll
            for (int j = 0; j < 4; j++) {
                uint2 hw, lw;
                split2(ar[j].x, ar[j].y, hw.x, lw.x);
                split2(ar[j].z, ar[j].w, hw.y, lw.y);
                *(uint2*)(ah + j * 4) = hw;
                *(uint2*)(al + j * 4) = lw;
            }
            *(uint2*)(Bhs + p * 32 * BPITCH + bk * BPITCH + bn) = bhr;
            *(uint2*)(Bls + p * 32 * BPITCH + bk * BPITCH + bn) = blr;
        }
        __syncthreads();
        if (c + 1 < c1) {
            int kb = (c + 1) * 32;
#pragma unroll
            for (int j = 0; j < 4; j++)
                ar[j] = aval ? *(const float4*)(Arow + kb + j * 4) : make_float4(0,0,0,0);
            bhr = *(const uint2*)(g_Bh + (size_t)(kb + bk) * 32 + bn);
            blr = *(const uint2*)(g_Bl + (size_t)(kb + bk) * 32 + bn);
        }
        uint32_t ahB = (uint32_t)__cvta_generic_to_shared(Ah + p * 128 * APITCH);
        uint32_t alB = (uint32_t)__cvta_generic_to_shared(Al + p * 128 * APITCH);
        uint32_t bhB = (uint32_t)__cvta_generic_to_shared(Bhs + p * 32 * BPITCH);
        uint32_t blB = (uint32_t)__cvta_generic_to_shared(Bls + p * 32 * BPITCH);
#pragma unroll
        for (int kk = 0; kk < 2; kk++) {
            uint32_t ahf[2][4], alf[2][4], bhf[2][2], blf[2][2];
#pragma unroll
            for (int mt = 0; mt < 2; mt++) {
                int row = wm * 32 + mt * 16 + (lane & 15);
                int col = kk * 16 + (lane >> 4) * 8;
                uint32_t off = (uint32_t)(row * APITCH + col) * 2;
                LDSM4(ahf[mt], ahB + off);
                LDSM4(alf[mt], alB + off);
            }
#pragma unroll
            for (int nt = 0; nt < 2; nt++) {
                int krow = kk * 16 + (lane & 15);
                int ncol = wn * 16 + nt * 8;
                uint32_t off = (uint32_t)(krow * BPITCH + ncol) * 2;
                LDSM2T(bhf[nt], bhB + off);
                LDSM2T(blf[nt], blB + off);
            }
#pragma unroll
            for (int mt = 0; mt < 2; mt++)
#pragma unroll
                for (int nt = 0; nt < 2; nt++) {
                    MMABF16(d[mt][nt], ahf[mt], bhf[nt]);
                    MMABF16(d[mt][nt], ahf[mt], blf[nt]);
                    MMABF16(d[mt][nt], alf[mt], bhf[nt]);
                }
        }
        p ^= 1;
    }
    float* slab = g_Pf + (size_t)blockIdx.y * Mrows * 32;
    int g = lane >> 2, t4 = lane & 3;
#pragma unroll
    for (int mt = 0; mt < 2; mt++)
#pragma unroll
        for (int nt = 0; nt < 2; nt++) {
            int i0 = ibase + wm * 32 + mt * 16 + g;
            int b0 = wn * 16 + nt * 8 + t4 * 2;
            *(float2*)(slab + (size_t)i0 * 32 + b0)       = make_float2(d[mt][nt][0], d[mt][nt][1]);
            *(float2*)(slab + (size_t)(i0 + 8) * 32 + b0) = make_float2(d[mt][nt][2], d[mt][nt][3]);
        }
}

// ---------------- fold K-split partials -> coeff, s[b] = sum coeff^2 ------
__global__ void k_reduce(int phase) {
    __shared__ float sAcc[32];
    int tid = threadIdx.x;
    if (tid < 32) sAcc[tid] = 0.f;
    __syncthreads();
    int Ksp   = phase ? KS2 : KS1;
    int Mrows = phase ? MR2 : MR1;
    int M     = phase ? N12c : N1c;
    float* coeff = phase ? g_cz : g_cy;
    float* sOut  = phase ? g_sz : g_sy;
    int u = blockIdx.x * 256 + tid;
    int b = u & 31;
    if (u < M * 32) {
        float s = 0.f;
        for (int j = 0; j < Ksp; j++) s += g_Pf[(size_t)j * Mrows * 32 + u];
        coeff[u] = s;
        atomicAdd(&sAcc[b], s * s);
    }
    __syncthreads();
    if (tid < 32) atomicAdd(&sOut[tid], sAcc[tid]);
}

// ---------------- apply rank-1 y correction to vertices < N1 --------------
__global__ void k_upy() {
    int u = blockIdx.x * 256 + threadIdx.x;
    if (u >= N1c * Bz) return;
    int b = u & 31;
    g_py[u] += g_cy[u] * (g_a[b] / g_sy[b]);
}

// ---------------- final outputs (z correction applied on the fly) ---------
__global__ void k_out(float* __restrict__ out) {
    int u = blockIdx.x * 256 + threadIdx.x;
    if (u >= N12c * Bz) return;
    int v = u >> 5, b = u & 31;
    float corr = g_cz[u] * (g_a[b] / g_sz[b]);
    float X = g_px[u], Z = g_pz[u] + corr;
    if (v < N1c) {
        float* o = out + (size_t)b * (N1c * 3) + v * 3;
        o[0] = X; o[1] = g_py[u]; o[2] = Z;
    } else {
        int j = v - N1c;
        float* o = out + (size_t)Bz * N1c * 3 + (size_t)b * (N2c * 2) + j * 2;
        o[0] = X; o[1] = Z;
    }
}

extern "C" void kernel_launch(void* const* d_in, const int* in_sizes, int n_in,
                              void* d_out, int out_size) {
    const float* x   = (const float*)d_in[0];
    const float* y   = (const float*)d_in[1];
    const float* p0  = (const float*)d_in[2];
    const int*   tri = (const int*)d_in[3];
    const float* Vx  = (const float*)d_in[6];
    const float* Vxy = (const float*)d_in[7];
    float* out = (float*)d_out;
    (void)in_sizes; (void)n_in; (void)out_size;

    const int smemB = (2 * 128 * APITCH + 2 * 128 * APITCH / 1 * 0 +
                       2 * 128 * APITCH) * 0 +  // (computed below)
                      (2 * 128 * APITCH * 2 + 2 * 32 * BPITCH * 2) * 2; // bytes
    static bool attrSet = false;
    if (!attrSet) {
        cudaFuncSetAttribute(k_gemm_tc, cudaFuncAttributeMaxDynamicSharedMemorySize, smemB);
        attrSet = true;
    }

    k_init<<<1500, 256>>>(x, y, p0);
    k_det<<<1250, 256>>>(tri, p0, 0);
    k_a<<<1, 256>>>();
    k_gemm_tc<<<dim3(MT1, KS1), 256, smemB>>>(Vx, N1c, MR1, CPS1);
    k_reduce<<<500, 256>>>(0);
    k_upy<<<500, 256>>>();
    k_det<<<1250, 256>>>(tri, p0, 1);
    k_gemm_tc<<<dim3(MT2, KS2), 256, smemB>>>(Vxy, N12c, MR2, CPS2);
    k_reduce<<<625, 256>>>(1);
    k_out<<<625, 256>>>(out);
}

// round 5
// speedup vs baseline: 1.6489x; 1.1107x over previous
#include <cuda_runtime.h>
#include <cuda_bf16.h>
#include <cstdint>

#define Bz   32
#define NV   12000
#define NT   20000
#define N1c  4000
#define N2c  1000
#define N12c 5000
#define KKc  20000
#define KC   625            // 32-wide k-chunks (625*32 = 20000 exactly)

// GEMM1: 32 m-tiles (4096 rows), Ksplit 9 (70 chunks/split, last 65)
#define MT1 32
#define MR1 4096
#define KS1 9
#define CPS1 70
// GEMM2: 40 m-tiles (5120 rows), Ksplit 7 (90 chunks/split, last 85)
#define MT2 40
#define MR2 5120
#define KS2 7
#define CPS2 90

#define BPITCH 40   // bf16 elems per B smem row (80B, conflict-free ldmatrix)

// ---------------- device scratch (static; no allocations) ----------------
__device__ float  g_px[NV * Bz];            // [v*32 + b]
__device__ float  g_py[NV * Bz];
__device__ float  g_pz[NV * Bz];
__device__ __nv_bfloat16 g_Bh[NT * Bz];     // B hi split, [t*32 + b]
__device__ __nv_bfloat16 g_Bl[NT * Bz];     // B lo split
__device__ float  g_cy[N1c * Bz];           // coeffy [i*32 + b]
__device__ float  g_cz[N12c * Bz];
__device__ float  g_Pf[(size_t)KS1 * MR1 * 32];  // K-split partial slab
__device__ float2 g_volP[1250 * 16];
__device__ float  g_volcP[1250];
__device__ float  g_a[Bz];
__device__ float  g_sy[Bz];
__device__ float  g_sz[Bz];

// ---------------- K0: build SoA points (batch-fastest) + zero sums --------
__global__ void k_init(const float* __restrict__ x, const float* __restrict__ y,
                       const float* __restrict__ p0) {
    int u = blockIdx.x * 256 + threadIdx.x;
    if (u < 64) { if (u < 32) g_sy[u] = 0.f; else g_sz[u - 32] = 0.f; }
    if (u >= NV * Bz) return;
    int v = u >> 5, b = u & 31;
    float px, py, pz;
    if (v < N1c) {
        const float* xb = x + (size_t)b * (N1c * 3) + v * 3;
        px = xb[0]; py = xb[1]; pz = xb[2];
    } else if (v < N12c) {
        int j = v - N1c;
        const float* yb = y + (size_t)b * (N2c * 2) + j * 2;
        px = yb[0]; pz = yb[1]; py = p0[v * 3 + 1];
    } else {
        px = p0[v * 3]; py = p0[v * 3 + 1]; pz = p0[v * 3 + 2];
    }
    g_px[u] = px; g_py[u] = py; g_pz[u] = pz;
}

// helper: split a pair of floats into bf16 hi/lo packed words
__device__ __forceinline__ void split2(float f0, float f1, uint32_t& hw, uint32_t& lw) {
    __nv_bfloat162 h = __floats2bfloat162_rn(f0, f1);
    float r0 = f0 - __bfloat162float(h.x);
    float r1 = f1 - __bfloat162float(h.y);
    __nv_bfloat162 l = __floats2bfloat162_rn(r0, r1);
    hw = *(uint32_t*)&h; lw = *(uint32_t*)&l;
}

// ---------------- K1: per-triangle dets -> bf16-split B, + volume ---------
__global__ void k_det(const int* __restrict__ tri, const float* __restrict__ p0,
                      int phase) {
    __shared__ float2 sv[16];
    __shared__ float  sc;
    int tid = threadIdx.x;
    if (phase == 0) {
        if (tid < 16) sv[tid] = make_float2(0.f, 0.f);
        if (tid == 0) sc = 0.f;
        __syncthreads();
    }
    int u = blockIdx.x * 256 + tid;
    int t = u >> 4, b2 = u & 15;
    if (t < NT) {
        int v0 = tri[t * 3], v1 = tri[t * 3 + 1], v2 = tri[t * 3 + 2];
        const float2* PX = (const float2*)g_px;
        const float2* PY = (const float2*)g_py;
        const float2* PZ = (const float2*)g_pz;
        float2 x0 = PX[v0 * 16 + b2], x1 = PX[v1 * 16 + b2], x2 = PX[v2 * 16 + b2];
        float2 d;
        if (phase == 0) {
            float2 z0 = PZ[v0 * 16 + b2], z1 = PZ[v1 * 16 + b2], z2 = PZ[v2 * 16 + b2];
            float2 y0 = PY[v0 * 16 + b2], y1 = PY[v1 * 16 + b2], y2 = PY[v2 * 16 + b2];
            d.x = ((x0.x - x1.x) * (z2.x - z1.x) - (z0.x - z1.x) * (x2.x - x1.x)) * (1.f / 6.f);
            d.y = ((x0.y - x1.y) * (z2.y - z1.y) - (z0.y - z1.y) * (x2.y - x1.y)) * (1.f / 6.f);
            atomicAdd(&sv[b2].x, (y0.x + y1.x + y2.x) * d.x);
            atomicAdd(&sv[b2].y, (y0.y + y1.y + y2.y) * d.y);
            if (b2 == 0) {
                float X0 = p0[v0 * 3], Y0 = p0[v0 * 3 + 1], Z0 = p0[v0 * 3 + 2];
                float X1 = p0[v1 * 3], Y1 = p0[v1 * 3 + 1], Z1 = p0[v1 * 3 + 2];
                float X2 = p0[v2 * 3], Y2 = p0[v2 * 3 + 1], Z2 = p0[v2 * 3 + 2];
                float d0 = ((X0 - X1) * (Z2 - Z1) - (Z0 - Z1) * (X2 - X1)) * (1.f / 6.f);
                atomicAdd(&sc, (Y0 + Y1 + Y2) * d0);
            }
        } else {
            float2 y0 = PY[v0 * 16 + b2], y1 = PY[v1 * 16 + b2], y2 = PY[v2 * 16 + b2];
            d.x = ((x0.x - x2.x) * (y1.x - y2.x) - (y0.x - y2.x) * (x1.x - x2.x)) * (1.f / 6.f);
            d.y = ((x0.y - x2.y) * (y1.y - y2.y) - (y0.y - y2.y) * (x1.y - x2.y)) * (1.f / 6.f);
        }
        uint32_t hw, lw;
        split2(d.x, d.y, hw, lw);
        *(uint32_t*)(g_Bh + t * 32 + 2 * b2) = hw;
        *(uint32_t*)(g_Bl + t * 32 + 2 * b2) = lw;
    }
    if (phase == 0) {
        __syncthreads();
        if (tid < 16) g_volP[blockIdx.x * 16 + tid] = sv[tid];
        if (tid == 0) g_volcP[blockIdx.x] = sc;
    }
}

// ---------------- K2: reduce volume partials -> a[b] ----------------------
__global__ void k_a() {
    __shared__ float2 red[256];
    __shared__ float  redc[256];
    int tid = threadIdx.x;
    int b2 = tid & 15, r = tid >> 4;
    float2 s = make_float2(0.f, 0.f);
    for (int j = r; j < 1250; j += 16) {
        float2 v = g_volP[j * 16 + b2]; s.x += v.x; s.y += v.y;
    }
    red[tid] = s;
    float c = 0.f;
    for (int j = tid; j < 1250; j += 256) c += g_volcP[j];
    redc[tid] = c;
    __syncthreads();
    for (int h = 8; h > 0; h >>= 1) {
        if (r < h) { red[tid].x += red[tid + h * 16].x; red[tid].y += red[tid + h * 16].y; }
        __syncthreads();
    }
    for (int h = 128; h > 0; h >>= 1) {
        if (tid < h) redc[tid] += redc[tid + h];
        __syncthreads();
    }
    if (tid < 32) {
        float volc = redc[0];
        float2 vb = red[tid >> 1];
        float volb = (tid & 1) ? vb.y : vb.x;
        g_a[tid] = 0.5f * (volc - volb);
    }
}

// ---------------- tensor-core GEMM: A direct-from-gmem, B via smem --------
#define LDSM4T(r, addr) \
    asm volatile("ldmatrix.sync.aligned.m8n8.x4.trans.shared.b16 {%0,%1,%2,%3}, [%4];" \
        : "=r"((r)[0]), "=r"((r)[1]), "=r"((r)[2]), "=r"((r)[3]) : "r"(addr))
#define MMABF16(dd, aa, bb) \
    asm volatile("mma.sync.aligned.m16n8k16.row.col.f32.bf16.bf16.f32 " \
        "{%0,%1,%2,%3}, {%4,%5,%6,%7}, {%8,%9}, {%0,%1,%2,%3};" \
        : "+f"((dd)[0]), "+f"((dd)[1]), "+f"((dd)[2]), "+f"((dd)[3]) \
        : "r"((aa)[0]), "r"((aa)[1]), "r"((aa)[2]), "r"((aa)[3]), \
          "r"((bb)[0]), "r"((bb)[1]))

__global__ void __launch_bounds__(256, 2)
k_gemm_tc(const float* __restrict__ A, int M, int Mrows, int cps) {
    __shared__ __align__(16) __nv_bfloat16 Bhs[2][32 * BPITCH];
    __shared__ __align__(16) __nv_bfloat16 Bls[2][32 * BPITCH];

    int tid = threadIdx.x;
    int lane = tid & 31, w = tid >> 5;      // 8 warps, each owns m16 rows
    int g = lane >> 2, t4 = lane & 3;
    int ibase = blockIdx.x * 128;
    int c0 = blockIdx.y * cps;
    int c1 = min(KC, c0 + cps);

    int row0 = ibase + w * 16 + g;
    bool v0 = row0 < M, v8 = (row0 + 8) < M;
    const float* A0 = A + (size_t)row0 * KKc + t4 * 2;
    const float* A8 = A0 + (size_t)8 * KKc;

    int bk = tid >> 3, bn = (tid & 7) * 4;  // B staging: 32 rows x 32 cols
    const size_t bOff = (size_t)bk * 32 + bn;

    float2 ar[2][4];
    uint2 bhr, blr;

    // prefetch chunk c0
    {
        int kb = c0 * 32;
#pragma unroll
        for (int kk = 0; kk < 2; kk++) {
            int off = kb + kk * 16;
            ar[kk][0] = v0 ? *(const float2*)(A0 + off)     : make_float2(0.f, 0.f);
            ar[kk][1] = v8 ? *(const float2*)(A8 + off)     : make_float2(0.f, 0.f);
            ar[kk][2] = v0 ? *(const float2*)(A0 + off + 8) : make_float2(0.f, 0.f);
            ar[kk][3] = v8 ? *(const float2*)(A8 + off + 8) : make_float2(0.f, 0.f);
        }
        bhr = *(const uint2*)(g_Bh + (size_t)kb * 32 + bOff);
        blr = *(const uint2*)(g_Bl + (size_t)kb * 32 + bOff);
    }

    float d[4][4];
#pragma unroll
    for (int nt = 0; nt < 4; nt++)
#pragma unroll
        for (int q = 0; q < 4; q++) d[nt][q] = 0.f;

    int p = 0;
    for (int c = c0; c < c1; c++) {
        __syncthreads();
        *(uint2*)(&Bhs[p][bk * BPITCH + bn]) = bhr;
        *(uint2*)(&Bls[p][bk * BPITCH + bn]) = blr;
        __syncthreads();

        // convert current A fragments in registers (hi/lo split)
        uint32_t ahf[2][4], alf[2][4];
#pragma unroll
        for (int kk = 0; kk < 2; kk++)
#pragma unroll
            for (int j = 0; j < 4; j++)
                split2(ar[kk][j].x, ar[kk][j].y, ahf[kk][j], alf[kk][j]);

        // prefetch next chunk (in flight during compute)
        if (c + 1 < c1) {
            int kb = (c + 1) * 32;
#pragma unroll
            for (int kk = 0; kk < 2; kk++) {
                int off = kb + kk * 16;
                ar[kk][0] = v0 ? *(const float2*)(A0 + off)     : make_float2(0.f, 0.f);
                ar[kk][1] = v8 ? *(const float2*)(A8 + off)     : make_float2(0.f, 0.f);
                ar[kk][2] = v0 ? *(const float2*)(A0 + off + 8) : make_float2(0.f, 0.f);
                ar[kk][3] = v8 ? *(const float2*)(A8 + off + 8) : make_float2(0.f, 0.f);
            }
            bhr = *(const uint2*)(g_Bh + (size_t)kb * 32 + bOff);
            blr = *(const uint2*)(g_Bl + (size_t)kb * 32 + bOff);
        }

        // B fragments via ldmatrix.x4.trans (all 4 n8 tiles)
        uint32_t bhf[2][4][2], blf[2][4][2];
        uint32_t bhB = (uint32_t)__cvta_generic_to_shared(&Bhs[p][0]);
        uint32_t blB = (uint32_t)__cvta_generic_to_shared(&Bls[p][0]);
#pragma unroll
        for (int kk = 0; kk < 2; kk++)
#pragma unroll
            for (int ntp = 0; ntp < 2; ntp++) {
                int rrow = kk * 16 + (lane & 15);
                int rcol = ntp * 16 + (lane >> 4) * 8;
                uint32_t off = (uint32_t)(rrow * BPITCH + rcol) * 2;
                uint32_t t[4];
                LDSM4T(t, bhB + off);
                bhf[kk][ntp * 2][0] = t[0]; bhf[kk][ntp * 2][1] = t[1];
                bhf[kk][ntp * 2 + 1][0] = t[2]; bhf[kk][ntp * 2 + 1][1] = t[3];
                LDSM4T(t, blB + off);
                blf[kk][ntp * 2][0] = t[0]; blf[kk][ntp * 2][1] = t[1];
                blf[kk][ntp * 2 + 1][0] = t[2]; blf[kk][ntp * 2 + 1][1] = t[3];
            }

#pragma unroll
        for (int kk = 0; kk < 2; kk++)
#pragma unroll
            for (int nt = 0; nt < 4; nt++) {
                MMABF16(d[nt], ahf[kk], bhf[kk][nt]);
                MMABF16(d[nt], ahf[kk], blf[kk][nt]);
                MMABF16(d[nt], alf[kk], bhf[kk][nt]);
            }
        p ^= 1;
    }

    float* slab = g_Pf + (size_t)blockIdx.y * Mrows * 32;
#pragma unroll
    for (int nt = 0; nt < 4; nt++) {
        int n = nt * 8 + t4 * 2;
        *(float2*)(slab + (size_t)row0 * 32 + n)       = make_float2(d[nt][0], d[nt][1]);
        *(float2*)(slab + (size_t)(row0 + 8) * 32 + n) = make_float2(d[nt][2], d[nt][3]);
    }
}

// ---------------- fold K-split partials -> coeff, s[b] = sum coeff^2 ------
__global__ void k_reduce(int phase) {
    __shared__ float sAcc[32];
    int tid = threadIdx.x;
    if (tid < 32) sAcc[tid] = 0.f;
    __syncthreads();
    int Ksp   = phase ? KS2 : KS1;
    int Mrows = phase ? MR2 : MR1;
    int M     = phase ? N12c : N1c;
    float* coeff = phase ? g_cz : g_cy;
    float* sOut  = phase ? g_sz : g_sy;
    int u = blockIdx.x * 256 + tid;
    int b = u & 31;
    if (u < M * 32) {
        float s = 0.f;
        for (int j = 0; j < Ksp; j++) s += g_Pf[(size_t)j * Mrows * 32 + u];
        coeff[u] = s;
        atomicAdd(&sAcc[b], s * s);
    }
    __syncthreads();
    if (tid < 32) atomicAdd(&sOut[tid], sAcc[tid]);
}

// ---------------- apply rank-1 y correction to vertices < N1 --------------
__global__ void k_upy() {
    int u = blockIdx.x * 256 + threadIdx.x;
    if (u >= N1c * Bz) return;
    int b = u & 31;
    g_py[u] += g_cy[u] * (g_a[b] / g_sy[b]);
}

// ---------------- final outputs (z correction applied on the fly) ---------
__global__ void k_out(float* __restrict__ out) {
    int u = blockIdx.x * 256 + threadIdx.x;
    if (u >= N12c * Bz) return;
    int v = u >> 5, b = u & 31;
    float corr = g_cz[u] * (g_a[b] / g_sz[b]);
    float X = g_px[u], Z = g_pz[u] + corr;
    if (v < N1c) {
        float* o = out + (size_t)b * (N1c * 3) + v * 3;
        o[0] = X; o[1] = g_py[u]; o[2] = Z;
    } else {
        int j = v - N1c;
        float* o = out + (size_t)Bz * N1c * 3 + (size_t)b * (N2c * 2) + j * 2;
        o[0] = X; o[1] = Z;
    }
}

extern "C" void kernel_launch(void* const* d_in, const int* in_sizes, int n_in,
                              void* d_out, int out_size) {
    const float* x   = (const float*)d_in[0];
    const float* y   = (const float*)d_in[1];
    const float* p0  = (const float*)d_in[2];
    const int*   tri = (const int*)d_in[3];
    const float* Vx  = (const float*)d_in[6];
    const float* Vxy = (const float*)d_in[7];
    float* out = (float*)d_out;
    (void)in_sizes; (void)n_in; (void)out_size;

    k_init<<<1500, 256>>>(x, y, p0);
    k_det<<<1250, 256>>>(tri, p0, 0);
    k_a<<<1, 256>>>();
    k_gemm_tc<<<dim3(MT1, KS1), 256>>>(Vx, N1c, MR1, CPS1);
    k_reduce<<<500, 256>>>(0);
    k_upy<<<500, 256>>>();
    k_det<<<1250, 256>>>(tri, p0, 1);
    k_gemm_tc<<<dim3(MT2, KS2), 256>>>(Vxy, N12c, MR2, CPS2);
    k_reduce<<<625, 256>>>(1);
    k_out<<<625, 256>>>(out);
}

// round 6
// speedup vs baseline: 1.8379x; 1.1146x over previous
#include <cuda_runtime.h>
#include <cuda_bf16.h>
#include <cstdint>

#define Bz   32
#define NV   12000
#define NT   20000
#define N1c  4000
#define N2c  1000
#define N12c 5000
#define KKc  20000
#define KC   625            // 32-wide k-chunks (625*32 = 20000 exactly)

// GEMM1: 32 m-tiles (4096 rows), Ksplit 9 (70 chunks/split, last 65)
#define MT1 32
#define MR1 4096
#define KS1 9
#define CPS1 70
// GEMM2: 40 m-tiles (5120 rows), Ksplit 7 (90 chunks/split, last 85)
#define MT2 40
#define MR2 5120
#define KS2 7
#define CPS2 90

#define BPITCH 40   // bf16 elems per B smem row (80B, conflict-free ldmatrix)

// ---------------- device scratch (static; no allocations) ----------------
__device__ float  g_px[NV * Bz];            // [v*32 + b]
__device__ float  g_py[NV * Bz];
__device__ float  g_pz[NV * Bz];
__device__ __nv_bfloat16 g_Bh[NT * Bz];     // B hi split, rows k-permuted per 16
__device__ __nv_bfloat16 g_Bl[NT * Bz];     // B lo split
__device__ float  g_cy[N1c * Bz];           // coeffy [i*32 + b]
__device__ float  g_cz[N12c * Bz];
__device__ float  g_Pf[(size_t)KS1 * MR1 * 32];  // K-split partial slab
__device__ float2 g_volP[1250 * 16];
__device__ float  g_volcP[1250];
__device__ float  g_a[Bz];
__device__ float  g_sy[Bz];
__device__ float  g_sz[Bz];

// k-permutation within each 16-group: physical pair q -> logical pair
// (q even ? q/2 : 4 + q/2). Makes A float4 halves = MMA a01/a45 directly.
__device__ __forceinline__ int kperm(int p) {
    int q = p >> 1;
    int lp = (q & 1) ? 4 + (q >> 1) : (q >> 1);
    return lp * 2 + (p & 1);
}

// ---------------- K0: build SoA points (batch-fastest) + zero sums --------
__global__ void k_init(const float* __restrict__ x, const float* __restrict__ y,
                       const float* __restrict__ p0) {
    int u = blockIdx.x * 256 + threadIdx.x;
    if (u < 64) { if (u < 32) g_sy[u] = 0.f; else g_sz[u - 32] = 0.f; }
    if (u >= NV * Bz) return;
    int v = u >> 5, b = u & 31;
    float px, py, pz;
    if (v < N1c) {
        const float* xb = x + (size_t)b * (N1c * 3) + v * 3;
        px = xb[0]; py = xb[1]; pz = xb[2];
    } else if (v < N12c) {
        int j = v - N1c;
        const float* yb = y + (size_t)b * (N2c * 2) + j * 2;
        px = yb[0]; pz = yb[1]; py = p0[v * 3 + 1];
    } else {
        px = p0[v * 3]; py = p0[v * 3 + 1]; pz = p0[v * 3 + 2];
    }
    g_px[u] = px; g_py[u] = py; g_pz[u] = pz;
}

// helper: split a pair of floats into bf16 hi/lo packed words
__device__ __forceinline__ void split2(float f0, float f1, uint32_t& hw, uint32_t& lw) {
    __nv_bfloat162 h = __floats2bfloat162_rn(f0, f1);
    float r0 = f0 - __bfloat162float(h.x);
    float r1 = f1 - __bfloat162float(h.y);
    __nv_bfloat162 l = __floats2bfloat162_rn(r0, r1);
    hw = *(uint32_t*)&h; lw = *(uint32_t*)&l;
}

// ---------------- K1: per-triangle dets -> bf16-split B (permuted rows) ---
__global__ void k_det(const int* __restrict__ tri, const float* __restrict__ p0,
                      int phase) {
    __shared__ float2 sv[16];
    __shared__ float  sc;
    int tid = threadIdx.x;
    if (phase == 0) {
        if (tid < 16) sv[tid] = make_float2(0.f, 0.f);
        if (tid == 0) sc = 0.f;
        __syncthreads();
    }
    int u = blockIdx.x * 256 + tid;
    int t = u >> 4, b2 = u & 15;
    if (t < NT) {
        int v0 = tri[t * 3], v1 = tri[t * 3 + 1], v2 = tri[t * 3 + 2];
        const float2* PX = (const float2*)g_px;
        const float2* PY = (const float2*)g_py;
        const float2* PZ = (const float2*)g_pz;
        float2 x0 = PX[v0 * 16 + b2], x1 = PX[v1 * 16 + b2], x2 = PX[v2 * 16 + b2];
        float2 d;
        if (phase == 0) {
            float2 z0 = PZ[v0 * 16 + b2], z1 = PZ[v1 * 16 + b2], z2 = PZ[v2 * 16 + b2];
            float2 y0 = PY[v0 * 16 + b2], y1 = PY[v1 * 16 + b2], y2 = PY[v2 * 16 + b2];
            d.x = ((x0.x - x1.x) * (z2.x - z1.x) - (z0.x - z1.x) * (x2.x - x1.x)) * (1.f / 6.f);
            d.y = ((x0.y - x1.y) * (z2.y - z1.y) - (z0.y - z1.y) * (x2.y - x1.y)) * (1.f / 6.f);
            atomicAdd(&sv[b2].x, (y0.x + y1.x + y2.x) * d.x);
            atomicAdd(&sv[b2].y, (y0.y + y1.y + y2.y) * d.y);
            if (b2 == 0) {
                float X0 = p0[v0 * 3], Y0 = p0[v0 * 3 + 1], Z0 = p0[v0 * 3 + 2];
                float X1 = p0[v1 * 3], Y1 = p0[v1 * 3 + 1], Z1 = p0[v1 * 3 + 2];
                float X2 = p0[v2 * 3], Y2 = p0[v2 * 3 + 1], Z2 = p0[v2 * 3 + 2];
                float d0 = ((X0 - X1) * (Z2 - Z1) - (Z0 - Z1) * (X2 - X1)) * (1.f / 6.f);
                atomicAdd(&sc, (Y0 + Y1 + Y2) * d0);
            }
        } else {
            float2 y0 = PY[v0 * 16 + b2], y1 = PY[v1 * 16 + b2], y2 = PY[v2 * 16 + b2];
            d.x = ((x0.x - x2.x) * (y1.x - y2.x) - (y0.x - y2.x) * (x1.x - x2.x)) * (1.f / 6.f);
            d.y = ((x0.y - x2.y) * (y1.y - y2.y) - (y0.y - y2.y) * (x1.y - x2.y)) * (1.f / 6.f);
        }
        uint32_t hw, lw;
        split2(d.x, d.y, hw, lw);
        int tp = (t & ~15) | kperm(t & 15);   // permuted row for GEMM
        *(uint32_t*)(g_Bh + tp * 32 + 2 * b2) = hw;
        *(uint32_t*)(g_Bl + tp * 32 + 2 * b2) = lw;
    }
    if (phase == 0) {
        __syncthreads();
        if (tid < 16) g_volP[blockIdx.x * 16 + tid] = sv[tid];
        if (tid == 0) g_volcP[blockIdx.x] = sc;
    }
}

// ---------------- K2: reduce volume partials -> a[b] ----------------------
__global__ void k_a() {
    __shared__ float2 red[256];
    __shared__ float  redc[256];
    int tid = threadIdx.x;
    int b2 = tid & 15, r = tid >> 4;
    float2 s = make_float2(0.f, 0.f);
    for (int j = r; j < 1250; j += 16) {
        float2 v = g_volP[j * 16 + b2]; s.x += v.x; s.y += v.y;
    }
    red[tid] = s;
    float c = 0.f;
    for (int j = tid; j < 1250; j += 256) c += g_volcP[j];
    redc[tid] = c;
    __syncthreads();
    for (int h = 8; h > 0; h >>= 1) {
        if (r < h) { red[tid].x += red[tid + h * 16].x; red[tid].y += red[tid + h * 16].y; }
        __syncthreads();
    }
    for (int h = 128; h > 0; h >>= 1) {
        if (tid < h) redc[tid] += redc[tid + h];
        __syncthreads();
    }
    if (tid < 32) {
        float volc = redc[0];
        float2 vb = red[tid >> 1];
        float volb = (tid & 1) ? vb.y : vb.x;
        g_a[tid] = 0.5f * (volc - volb);
    }
}

// ---------------- tensor-core GEMM: A LDG.128 direct, B via 4-chunk smem --
#define LDSM4T(r, addr) \
    asm volatile("ldmatrix.sync.aligned.m8n8.x4.trans.shared.b16 {%0,%1,%2,%3}, [%4];" \
        : "=r"((r)[0]), "=r"((r)[1]), "=r"((r)[2]), "=r"((r)[3]) : "r"(addr))
#define MMABF16(dd, aa, bb) \
    asm volatile("mma.sync.aligned.m16n8k16.row.col.f32.bf16.bf16.f32 " \
        "{%0,%1,%2,%3}, {%4,%5,%6,%7}, {%8,%9}, {%0,%1,%2,%3};" \
        : "+f"((dd)[0]), "+f"((dd)[1]), "+f"((dd)[2]), "+f"((dd)[3]) \
        : "r"((aa)[0]), "r"((aa)[1]), "r"((aa)[2]), "r"((aa)[3]), \
          "r"((bb)[0]), "r"((bb)[1]))

__global__ void __launch_bounds__(256, 2)
k_gemm_tc(const float* __restrict__ A, int M, int Mrows, int cps) {
    __shared__ __align__(16) __nv_bfloat16 Bhs[4][32 * BPITCH];
    __shared__ __align__(16) __nv_bfloat16 Bls[4][32 * BPITCH];

    int tid = threadIdx.x;
    int lane = tid & 31, w = tid >> 5;      // 8 warps, each owns m16 rows
    int g = lane >> 2, t4 = lane & 3;
    int ibase = blockIdx.x * 128;
    int c0 = blockIdx.y * cps;
    int c1 = min(KC, c0 + cps);

    int row0 = ibase + w * 16 + g;
    bool v0 = row0 < M, v8 = (row0 + 8) < M;
    const float* A0 = A + (size_t)row0 * KKc + t4 * 4;
    const float* A8 = A0 + (size_t)8 * KKc;

    int bk = tid >> 3, bn = (tid & 7) * 4;  // B staging: 32 rows x 32 cols
    const size_t bOff = (size_t)bk * 32 + bn;

    float4 ar[2][2];    // [row r][kk]
    uint2 bhr[4], blr[4];
    const float4 z4 = make_float4(0.f, 0.f, 0.f, 0.f);

    // prefetch A chunk c0
    {
        int kb = c0 * 32;
        ar[0][0] = v0 ? *(const float4*)(A0 + kb)      : z4;
        ar[0][1] = v0 ? *(const float4*)(A0 + kb + 16) : z4;
        ar[1][0] = v8 ? *(const float4*)(A8 + kb)      : z4;
        ar[1][1] = v8 ? *(const float4*)(A8 + kb + 16) : z4;
    }
    // prefetch B group [c0, c0+4)
#pragma unroll
    for (int j = 0; j < 4; j++) {
        int c = c0 + j;
        if (c < c1) {
            bhr[j] = *(const uint2*)(g_Bh + (size_t)c * 32 * 32 + bOff);
            blr[j] = *(const uint2*)(g_Bl + (size_t)c * 32 * 32 + bOff);
        }
    }

    float d[4][4];
#pragma unroll
    for (int nt = 0; nt < 4; nt++)
#pragma unroll
        for (int q = 0; q < 4; q++) d[nt][q] = 0.f;

    for (int cb = c0; cb < c1; cb += 4) {
        __syncthreads();
#pragma unroll
        for (int j = 0; j < 4; j++)
            if (cb + j < c1) {
                *(uint2*)(&Bhs[j][bk * BPITCH + bn]) = bhr[j];
                *(uint2*)(&Bls[j][bk * BPITCH + bn]) = blr[j];
            }
        __syncthreads();
        // prefetch next B group (flies during compute of this group)
#pragma unroll
        for (int j = 0; j < 4; j++) {
            int c = cb + 4 + j;
            if (c < c1) {
                bhr[j] = *(const uint2*)(g_Bh + (size_t)c * 32 * 32 + bOff);
                blr[j] = *(const uint2*)(g_Bl + (size_t)c * 32 * 32 + bOff);
            }
        }
#pragma unroll
        for (int j = 0; j < 4; j++) {
            int c = cb + j;
            if (c >= c1) continue;
            // A fragments: float4 halves are a01/a45 directly (k-permuted B)
            uint32_t ahf[2][4], alf[2][4];
#pragma unroll
            for (int kk = 0; kk < 2; kk++) {
                split2(ar[0][kk].x, ar[0][kk].y, ahf[kk][0], alf[kk][0]);
                split2(ar[1][kk].x, ar[1][kk].y, ahf[kk][1], alf[kk][1]);
                split2(ar[0][kk].z, ar[0][kk].w, ahf[kk][2], alf[kk][2]);
                split2(ar[1][kk].z, ar[1][kk].w, ahf[kk][3], alf[kk][3]);
            }
            // prefetch A chunk c+1
            if (c + 1 < c1) {
                int kb = (c + 1) * 32;
                ar[0][0] = v0 ? *(const float4*)(A0 + kb)      : z4;
                ar[0][1] = v0 ? *(const float4*)(A0 + kb + 16) : z4;
                ar[1][0] = v8 ? *(const float4*)(A8 + kb)      : z4;
                ar[1][1] = v8 ? *(const float4*)(A8 + kb + 16) : z4;
            }
            // B fragments via ldmatrix.x4.trans from slab j
            uint32_t bhf[2][4][2], blf[2][4][2];
            uint32_t bhB = (uint32_t)__cvta_generic_to_shared(&Bhs[j][0]);
            uint32_t blB = (uint32_t)__cvta_generic_to_shared(&Bls[j][0]);
#pragma unroll
            for (int kk = 0; kk < 2; kk++)
#pragma unroll
                for (int ntp = 0; ntp < 2; ntp++) {
                    int rrow = kk * 16 + (lane & 15);
                    int rcol = ntp * 16 + (lane >> 4) * 8;
                    uint32_t off = (uint32_t)(rrow * BPITCH + rcol) * 2;
                    uint32_t t[4];
                    LDSM4T(t, bhB + off);
                    bhf[kk][ntp * 2][0] = t[0]; bhf[kk][ntp * 2][1] = t[1];
                    bhf[kk][ntp * 2 + 1][0] = t[2]; bhf[kk][ntp * 2 + 1][1] = t[3];
                    LDSM4T(t, blB + off);
                    blf[kk][ntp * 2][0] = t[0]; blf[kk][ntp * 2][1] = t[1];
                    blf[kk][ntp * 2 + 1][0] = t[2]; blf[kk][ntp * 2 + 1][1] = t[3];
                }
#pragma unroll
            for (int kk = 0; kk < 2; kk++)
#pragma unroll
                for (int nt = 0; nt < 4; nt++) {
                    MMABF16(d[nt], ahf[kk], bhf[kk][nt]);
                    MMABF16(d[nt], ahf[kk], blf[kk][nt]);
                    MMABF16(d[nt], alf[kk], bhf[kk][nt]);
                }
        }
    }

    float* slab = g_Pf + (size_t)blockIdx.y * Mrows * 32;
#pragma unroll
    for (int nt = 0; nt < 4; nt++) {
        int n = nt * 8 + t4 * 2;
        *(float2*)(slab + (size_t)row0 * 32 + n)       = make_float2(d[nt][0], d[nt][1]);
        *(float2*)(slab + (size_t)(row0 + 8) * 32 + n) = make_float2(d[nt][2], d[nt][3]);
    }
}

// ---------------- fold K-split partials -> coeff, s[b] = sum coeff^2 ------
__global__ void k_reduce(int phase) {
    __shared__ float sAcc[32];
    int tid = threadIdx.x;
    if (tid < 32) sAcc[tid] = 0.f;
    __syncthreads();
    int Ksp   = phase ? KS2 : KS1;
    int Mrows = phase ? MR2 : MR1;
    int M     = phase ? N12c : N1c;
    float* coeff = phase ? g_cz : g_cy;
    float* sOut  = phase ? g_sz : g_sy;
    int u = blockIdx.x * 256 + tid;
    int b = u & 31;
    if (u < M * 32) {
        float s = 0.f;
        for (int j = 0; j < Ksp; j++) s += g_Pf[(size_t)j * Mrows * 32 + u];
        coeff[u] = s;
        atomicAdd(&sAcc[b], s * s);
    }
    __syncthreads();
    if (tid < 32) atomicAdd(&sOut[tid], sAcc[tid]);
}

// ---------------- apply rank-1 y correction to vertices < N1 --------------
__global__ void k_upy() {
    int u = blockIdx.x * 256 + threadIdx.x;
    if (u >= N1c * Bz) return;
    int b = u & 31;
    g_py[u] += g_cy[u] * (g_a[b] / g_sy[b]);
}

// ---------------- final outputs (z correction applied on the fly) ---------
__global__ void k_out(float* __restrict__ out) {
    int u = blockIdx.x * 256 + threadIdx.x;
    if (u >= N12c * Bz) return;
    int v = u >> 5, b = u & 31;
    float corr = g_cz[u] * (g_a[b] / g_sz[b]);
    float X = g_px[u], Z = g_pz[u] + corr;
    if (v < N1c) {
        float* o = out + (size_t)b * (N1c * 3) + v * 3;
        o[0] = X; o[1] = g_py[u]; o[2] = Z;
    } else {
        int j = v - N1c;
        float* o = out + (size_t)Bz * N1c * 3 + (size_t)b * (N2c * 2) + j * 2;
        o[0] = X; o[1] = Z;
    }
}

extern "C" void kernel_launch(void* const* d_in, const int* in_sizes, int n_in,
                              void* d_out, int out_size) {
    const float* x   = (const float*)d_in[0];
    const float* y   = (const float*)d_in[1];
    const float* p0  = (const float*)d_in[2];
    const int*   tri = (const int*)d_in[3];
    const float* Vx  = (const float*)d_in[6];
    const float* Vxy = (const float*)d_in[7];
    float* out = (float*)d_out;
    (void)in_sizes; (void)n_in; (void)out_size;

    k_init<<<1500, 256>>>(x, y, p0);
    k_det<<<1250, 256>>>(tri, p0, 0);
    k_a<<<1, 256>>>();
    k_gemm_tc<<<dim3(MT1, KS1), 256>>>(Vx, N1c, MR1, CPS1);
    k_reduce<<<500, 256>>>(0);
    k_upy<<<500, 256>>>();
    k_det<<<1250, 256>>>(tri, p0, 1);
    k_gemm_tc<<<dim3(MT2, KS2), 256>>>(Vxy, N12c, MR2, CPS2);
    k_reduce<<<625, 256>>>(1);
    k_out<<<625, 256>>>(out);
}